// round 1
// baseline (speedup 1.0000x reference)
#include <cuda_runtime.h>

// Problem constants
constexpr int LL    = 4096;                 // sequence length == kernel size
constexpr int NB    = 16;                   // batch
constexpr int NCIN  = 128;
constexpr int NCOUT = 128;
constexpr int KTOT  = NCIN * LL;            // 524288 = 2^19 reduction length
constexpr int NB2   = NB / 2;               // 8 batch pairs (f32x2 packing)

// GEMM blocking
constexpr int KS_SPLITS = 256;              // k-split blocks
constexpr int K_CHUNK   = KTOT / KS_SPLITS; // 2048
constexpr int STAGE_K   = 512;              // k per smem stage
constexpr int NSTAGES   = K_CHUNK / STAGE_K;// 4
constexpr int TOW       = 4;                // outputs per warp
constexpr int TOB       = 32;               // outputs per block (8 warps * 4)
constexpr int OGROUPS   = NCOUT / TOB;      // 4

// Scratch (allocation-free: __device__ globals)
__device__ float2 g_xp[NB2 * KTOT];                    // 32 MB reversed+pair-packed x
__device__ float  g_part[KS_SPLITS * NB * NCOUT];      // 2 MB partial sums

__device__ __forceinline__ unsigned long long dup_f32x2(float v) {
    unsigned long long r;
    asm("mov.b64 %0, {%1, %1};" : "=l"(r) : "f"(v));
    return r;
}
__device__ __forceinline__ void fma_f32x2(unsigned long long& d,
                                          unsigned long long a,
                                          unsigned long long b) {
    asm("fma.rn.f32x2 %0, %1, %2, %0;" : "+l"(d) : "l"(a), "l"(b));
}
__device__ __forceinline__ void add_f32x2(unsigned long long& d,
                                          unsigned long long a) {
    asm("add.rn.f32x2 %0, %0, %1;" : "+l"(d) : "l"(a));
}

// ---------------------------------------------------------------------------
// Kernel 1: build g_xp[b2][k] = { x[2b2, k_rev], x[2b2+1, k_rev] }
// where for k = i*L + m, k_rev = i*L + ((L - m) & (L-1)).
// ---------------------------------------------------------------------------
__global__ void prep_kernel(const float* __restrict__ x) {
    int idx = blockIdx.x * blockDim.x + threadIdx.x;   // 0 .. NB2*KTOT-1
    int b2  = idx >> 19;                               // / KTOT
    int k   = idx & (KTOT - 1);
    int m   = k & (LL - 1);
    int rev = (LL - m) & (LL - 1);
    int ksrc = (k & ~(LL - 1)) | rev;
    float lo = x[(size_t)(2 * b2)     * KTOT + ksrc];
    float hi = x[(size_t)(2 * b2 + 1) * KTOT + ksrc];
    g_xp[idx] = make_float2(lo, hi);
}

// ---------------------------------------------------------------------------
// Kernel 2: blocked GEMM. Block = (k-split, o-group of 32). 8 warps; each warp
// owns 4 output channels; all warps share the staged x chunk via SMEM.
// Accumulators are packed f32x2 (even batch in lo, odd batch in hi).
// ---------------------------------------------------------------------------
__global__ __launch_bounds__(256) void gemm_kernel(const float* __restrict__ w) {
    __shared__ float2 s_xp[NB2][STAGE_K];              // 32 KB

    const int ks   = blockIdx.x;                       // 0..KS_SPLITS-1
    const int og   = blockIdx.y;                       // 0..OGROUPS-1
    const int tid  = threadIdx.x;
    const int warp = tid >> 5;
    const int lane = tid & 31;
    const int o0   = og * TOB + warp * TOW;
    const int kbase = ks * K_CHUNK;

    const float2* __restrict__ w2 = reinterpret_cast<const float2*>(w);

    unsigned long long acc[NB2][TOW];
#pragma unroll
    for (int b2 = 0; b2 < NB2; b2++)
#pragma unroll
        for (int o = 0; o < TOW; o++) acc[b2][o] = 0ull;

    for (int s = 0; s < NSTAGES; s++) {
        const int k0 = kbase + s * STAGE_K;

        __syncthreads();
        // stage xp chunk: NB2 * STAGE_K float2 = 32 KB, float4 vectorized
#pragma unroll
        for (int t = tid; t < NB2 * (STAGE_K / 2); t += 256) {
            int b2 = t / (STAGE_K / 2);
            int kk = (t % (STAGE_K / 2)) * 2;
            *reinterpret_cast<float4*>(&s_xp[b2][kk]) =
                *reinterpret_cast<const float4*>(&g_xp[(size_t)b2 * KTOT + k0 + kk]);
        }
        __syncthreads();

#pragma unroll 2
        for (int it = 0; it < STAGE_K / 64; it++) {    // 8 iters, 2 k per lane
            const int kk  = (it * 32 + lane) * 2;      // local k (pair start)
            const int kg2 = (k0 + kk) >> 1;            // float2 index into w row

            float2 wv[TOW];
#pragma unroll
            for (int o = 0; o < TOW; o++)
                wv[o] = w2[(size_t)(o0 + o) * (KTOT / 2) + kg2];

            ulonglong2 xv[NB2];
#pragma unroll
            for (int b2 = 0; b2 < NB2; b2++)
                xv[b2] = *reinterpret_cast<const ulonglong2*>(&s_xp[b2][kk]);

#pragma unroll
            for (int o = 0; o < TOW; o++) {
                unsigned long long wd0 = dup_f32x2(wv[o].x);
                unsigned long long wd1 = dup_f32x2(wv[o].y);
#pragma unroll
                for (int b2 = 0; b2 < NB2; b2++) {
                    fma_f32x2(acc[b2][o], xv[b2].x, wd0);
                    fma_f32x2(acc[b2][o], xv[b2].y, wd1);
                }
            }
        }
    }

    // warp butterfly reduction (lane-partial sums -> lane 0)
#pragma unroll
    for (int off = 16; off > 0; off >>= 1) {
#pragma unroll
        for (int b2 = 0; b2 < NB2; b2++)
#pragma unroll
            for (int o = 0; o < TOW; o++) {
                unsigned long long other =
                    __shfl_xor_sync(0xffffffffu, acc[b2][o], off);
                add_f32x2(acc[b2][o], other);
            }
    }

    if (lane == 0) {
#pragma unroll
        for (int b2 = 0; b2 < NB2; b2++)
#pragma unroll
            for (int o = 0; o < TOW; o++) {
                float2 v;
                asm("mov.b64 {%0, %1}, %2;"
                    : "=f"(v.x), "=f"(v.y) : "l"(acc[b2][o]));
                g_part[((size_t)ks * NB + 2 * b2)     * NCOUT + o0 + o] = v.x;
                g_part[((size_t)ks * NB + 2 * b2 + 1) * NCOUT + o0 + o] = v.y;
            }
    }
}

// ---------------------------------------------------------------------------
// Kernel 3: deterministic final reduction over k-splits + bias.
// ---------------------------------------------------------------------------
__global__ void reduce_kernel(const float* __restrict__ bias,
                              float* __restrict__ out) {
    int idx = blockIdx.x * blockDim.x + threadIdx.x;   // b*NCOUT + o
    if (idx >= NB * NCOUT) return;
    int b = idx / NCOUT;
    int o = idx % NCOUT;
    float s = bias[o];
    for (int ks = 0; ks < KS_SPLITS; ks++)
        s += g_part[((size_t)ks * NB + b) * NCOUT + o];
    out[idx] = s;                                      // [B, COUT, 1] row-major
}

// ---------------------------------------------------------------------------
extern "C" void kernel_launch(void* const* d_in, const int* in_sizes, int n_in,
                              void* d_out, int out_size) {
    const float* x    = (const float*)d_in[0];   // [16, 128, 4096]
    const float* w    = (const float*)d_in[1];   // [128, 128, 4096]
    const float* bias = (const float*)d_in[2];   // [128]
    float* out = (float*)d_out;                  // [16, 128, 1] -> 2048 floats

    prep_kernel<<<(NB2 * KTOT) / 256, 256>>>(x);

    dim3 grid(KS_SPLITS, OGROUPS);
    gemm_kernel<<<grid, 256>>>(w);

    reduce_kernel<<<(NB * NCOUT + 255) / 256, 256>>>(bias, out);
}

// round 2
// speedup vs baseline: 1.0697x; 1.0697x over previous
#include <cuda_runtime.h>
#include <cstdint>

// Problem constants
constexpr int LL    = 4096;
constexpr int NB    = 16;
constexpr int NCIN  = 128;
constexpr int NCOUT = 128;
constexpr int KTOT  = NCIN * LL;            // 524288
constexpr int NB2   = NB / 2;               // 8 batch pairs (f32x2 packing)

// GEMM blocking
constexpr int KS        = 512;              // k-split blocks
constexpr int K_CHUNK   = KTOT / KS;        // 1024
constexpr int STAGE_K   = 256;              // k per smem stage
constexpr int NSTAGES   = K_CHUNK / STAGE_K;// 4
constexpr int TOW       = 8;                // outputs per warp
constexpr int TOB       = 64;               // outputs per block
constexpr int OGROUPS   = NCOUT / TOB;      // 2

// Scratch (allocation-free: __device__ globals)
__device__ __align__(16) float2 g_xp[NB2 * KTOT];          // 32 MB reversed+packed x
__device__ float g_part[NB * NCOUT * KS];                  // 4 MB, layout [b*NCOUT+o][ks]

__device__ __forceinline__ unsigned long long dup_f32x2(float v) {
    unsigned long long r;
    asm("mov.b64 %0, {%1, %1};" : "=l"(r) : "f"(v));
    return r;
}
__device__ __forceinline__ void fma_f32x2(unsigned long long& d,
                                          unsigned long long a,
                                          unsigned long long b) {
    asm("fma.rn.f32x2 %0, %1, %2, %0;" : "+l"(d) : "l"(a), "l"(b));
}
__device__ __forceinline__ void add_f32x2(unsigned long long& d,
                                          unsigned long long a) {
    asm("add.rn.f32x2 %0, %0, %1;" : "+l"(d) : "l"(a));
}

// ---------------------------------------------------------------------------
// Kernel 1: g_xp[b2][k] = { x[2b2, k_rev], x[2b2+1, k_rev] },
// k = i*L + m -> k_rev = i*L + ((L - m) & (L-1)).
// Source-aligned float4 loads; 4 scalar STG.64 (descending -> still coalesced).
// ---------------------------------------------------------------------------
__global__ void prep_kernel(const float* __restrict__ x) {
    int idx = blockIdx.x * blockDim.x + threadIdx.x;   // 0 .. NB2*KTOT/4-1
    int b2  = idx >> 17;                               // / (KTOT/4)
    int r   = idx & (KTOT / 4 - 1);
    int i   = r >> 10;                                 // / (LL/4)
    int t4  = r & (LL / 4 - 1);
    int sb  = i * LL + t4 * 4;
    float4 a = *reinterpret_cast<const float4*>(x + (size_t)(2 * b2) * KTOT + sb);
    float4 b = *reinterpret_cast<const float4*>(x + (size_t)(2 * b2 + 1) * KTOT + sb);
    float av[4] = {a.x, a.y, a.z, a.w};
    float bv[4] = {b.x, b.y, b.z, b.w};
#pragma unroll
    for (int e = 0; e < 4; e++) {
        int m = t4 * 4 + e;
        int k = i * LL + ((LL - m) & (LL - 1));
        g_xp[(size_t)b2 * KTOT + k] = make_float2(av[e], bv[e]);
    }
}

// ---------------------------------------------------------------------------
// Kernel 2: blocked split-K GEMM. Block = (ks, og). 8 warps x 8 outputs each.
// x staged through double-buffered smem via cp.async; acc packed f32x2.
// ---------------------------------------------------------------------------
__global__ __launch_bounds__(256, 1) void gemm_kernel(const float* __restrict__ w) {
    __shared__ __align__(16) float2 s_xp[2][NB2][STAGE_K];  // 2 x 16 KB

    const int ks   = blockIdx.x;
    const int og   = blockIdx.y;
    const int tid  = threadIdx.x;
    const int warp = tid >> 5;
    const int lane = tid & 31;
    const int o0   = og * TOB + warp * TOW;
    const int kbase = ks * K_CHUNK;

    const float2* __restrict__ w2 = reinterpret_cast<const float2*>(w);

    unsigned long long acc[NB2][TOW];
#pragma unroll
    for (int b2 = 0; b2 < NB2; b2++)
#pragma unroll
        for (int o = 0; o < TOW; o++) acc[b2][o] = 0ull;

    // cp.async prefetch of one stage: NB2*STAGE_K float2 = 16KB = 4 x 16B/thread
#define PREFETCH(S, BUF)                                                        \
    {                                                                           \
        const int k0s = kbase + (S) * STAGE_K;                                  \
        _Pragma("unroll")                                                       \
        for (int j = 0; j < 4; j++) {                                           \
            int lin = j * 256 + tid;                                            \
            int pb2 = lin >> 7;            /* / (STAGE_K/2) */                  \
            int pc  = lin & 127;                                                \
            const float2* src = &g_xp[(size_t)pb2 * KTOT + k0s + pc * 2];       \
            uint32_t dst = (uint32_t)__cvta_generic_to_shared(                  \
                &s_xp[BUF][pb2][pc * 2]);                                       \
            asm volatile("cp.async.cg.shared.global [%0], [%1], 16;\n"          \
                         :: "r"(dst), "l"(src));                                \
        }                                                                       \
        asm volatile("cp.async.commit_group;\n");                               \
    }

    PREFETCH(0, 0);

    for (int s = 0; s < NSTAGES; s++) {
        if (s + 1 < NSTAGES) {
            PREFETCH(s + 1, (s + 1) & 1);
            asm volatile("cp.async.wait_group 1;\n");
        } else {
            asm volatile("cp.async.wait_group 0;\n");
        }
        __syncthreads();

        const int buf = s & 1;
        const int kg2base = (kbase + s * STAGE_K) >> 1;

#pragma unroll 2
        for (int it = 0; it < STAGE_K / 64; it++) {    // 4 iters, 2 k per lane
            const int kk  = (it * 32 + lane) * 2;
            const int kg2 = kg2base + it * 32 + lane;

            float2 wv[TOW];
#pragma unroll
            for (int o = 0; o < TOW; o++)
                wv[o] = __ldg(&w2[(size_t)(o0 + o) * (KTOT / 2) + kg2]);

            ulonglong2 xv[NB2];
#pragma unroll
            for (int b2 = 0; b2 < NB2; b2++)
                xv[b2] = *reinterpret_cast<const ulonglong2*>(&s_xp[buf][b2][kk]);

#pragma unroll
            for (int o = 0; o < TOW; o++) {
                unsigned long long wd0 = dup_f32x2(wv[o].x);
                unsigned long long wd1 = dup_f32x2(wv[o].y);
#pragma unroll
                for (int b2 = 0; b2 < NB2; b2++) {
                    fma_f32x2(acc[b2][o], xv[b2].x, wd0);
                    fma_f32x2(acc[b2][o], xv[b2].y, wd1);
                }
            }
        }
        __syncthreads();
    }
#undef PREFETCH

    // Value-splitting butterfly: 64 accs -> each lane ends with accs 2l, 2l+1
    // fully reduced over all 32 lanes. ~62 shfl+add instead of 320.
    unsigned long long vals[64];
#pragma unroll
    for (int b2 = 0; b2 < NB2; b2++)
#pragma unroll
        for (int o = 0; o < TOW; o++) vals[b2 * TOW + o] = acc[b2][o];

#define RSTEP(OFF, CNT)                                                         \
    {                                                                           \
        const bool up = (lane & (OFF)) != 0;                                    \
        _Pragma("unroll")                                                       \
        for (int j = 0; j < (CNT); j++) {                                       \
            unsigned long long send = up ? vals[j] : vals[j + (CNT)];           \
            unsigned long long recv = __shfl_xor_sync(0xffffffffu, send, OFF);  \
            unsigned long long keep = up ? vals[j + (CNT)] : vals[j];           \
            add_f32x2(keep, recv);                                              \
            vals[j] = keep;                                                     \
        }                                                                       \
    }
    RSTEP(16, 32)
    RSTEP(8, 16)
    RSTEP(4, 8)
    RSTEP(2, 4)
    RSTEP(1, 2)
#undef RSTEP

#pragma unroll
    for (int j = 0; j < 2; j++) {
        int a  = 2 * lane + j;
        int b2 = a >> 3;       // vals layout [b2][o]
        int o  = a & 7;
        int oo = o0 + o;
        float2 v;
        asm("mov.b64 {%0, %1}, %2;" : "=f"(v.x), "=f"(v.y) : "l"(vals[j]));
        g_part[((size_t)(2 * b2)     * NCOUT + oo) * KS + ks] = v.x;
        g_part[((size_t)(2 * b2 + 1) * NCOUT + oo) * KS + ks] = v.y;
    }
}

// ---------------------------------------------------------------------------
// Kernel 3: deterministic reduction over k-splits + bias. One warp per output,
// coalesced over ks.
// ---------------------------------------------------------------------------
__global__ void reduce_kernel(const float* __restrict__ bias,
                              float* __restrict__ out) {
    int gw   = (blockIdx.x * blockDim.x + threadIdx.x) >> 5;  // output index
    int lane = threadIdx.x & 31;
    if (gw >= NB * NCOUT) return;
    const float* p = g_part + (size_t)gw * KS;
    float s = 0.0f;
#pragma unroll
    for (int i = 0; i < KS / 32; i++) s += p[i * 32 + lane];
#pragma unroll
    for (int off = 16; off > 0; off >>= 1)
        s += __shfl_xor_sync(0xffffffffu, s, off);
    if (lane == 0) out[gw] = s + bias[gw & (NCOUT - 1)];
}

// ---------------------------------------------------------------------------
extern "C" void kernel_launch(void* const* d_in, const int* in_sizes, int n_in,
                              void* d_out, int out_size) {
    const float* x    = (const float*)d_in[0];   // [16, 128, 4096]
    const float* w    = (const float*)d_in[1];   // [128, 128, 4096]
    const float* bias = (const float*)d_in[2];   // [128]
    float* out = (float*)d_out;                  // [16, 128, 1]

    prep_kernel<<<(NB2 * KTOT / 4) / 256, 256>>>(x);

    dim3 grid(KS, OGROUPS);
    gemm_kernel<<<grid, 256>>>(w);

    reduce_kernel<<<(NB * NCOUT * 32) / 256, 256>>>(bias, out);
}

// round 3
// speedup vs baseline: 1.3608x; 1.2721x over previous
#include <cuda_runtime.h>
#include <cstdint>

// Problem constants
constexpr int LL    = 4096;
constexpr int NB    = 16;
constexpr int NCIN  = 128;
constexpr int NCOUT = 128;
constexpr int KTOT  = NCIN * LL;            // 524288
constexpr int NB2   = NB / 2;               // 8 batch pairs (f32x2 packing)

// GEMM blocking
constexpr int KS        = 512;              // k-split blocks (each within one channel)
constexpr int K_CHUNK   = KTOT / KS;        // 1024
constexpr int STAGE_K   = 256;              // k per smem stage
constexpr int NSTAGES   = K_CHUNK / STAGE_K;// 4
constexpr int ITERS     = K_CHUNK / 64;     // 16 compute iters (64 k each)
constexpr int TOW       = 8;                // outputs per warp
constexpr int TOB       = 64;               // outputs per block
constexpr int OGROUPS   = NCOUT / TOB;      // 2

// Scratch (allocation-free)
__device__ float g_part[NB * NCOUT * KS];   // 4 MB, layout [b*NCOUT+o][ks]

__device__ __forceinline__ unsigned long long dup_f32x2(float v) {
    unsigned long long r;
    asm("mov.b64 %0, {%1, %1};" : "=l"(r) : "f"(v));
    return r;
}
__device__ __forceinline__ void fma_f32x2(unsigned long long& d,
                                          unsigned long long a,
                                          unsigned long long b) {
    asm("fma.rn.f32x2 %0, %1, %2, %0;" : "+l"(d) : "l"(a), "l"(b));
}
__device__ __forceinline__ void add_f32x2(unsigned long long& d,
                                          unsigned long long a) {
    asm("add.rn.f32x2 %0, %0, %1;" : "+l"(d) : "l"(a));
}

// ---------------------------------------------------------------------------
// Fused GEMM: out[b,o] = sum_k x[b, rev(k)] * w[o, k], split-K over 512 blocks.
// The index reversal (circular correlation at lag 0) is applied during smem
// staging, done with 4-byte cp.async gathers (descending-contiguous sources).
// 8 warps x 8 outputs; batches packed pairwise into f32x2 accumulators.
// Warp b2s==warp stages batch-pair `warp`'s slice each stage.
// ---------------------------------------------------------------------------
__global__ __launch_bounds__(256, 1) void gemm_kernel(const float* __restrict__ x,
                                                      const float* __restrict__ w) {
    __shared__ __align__(16) float2 s_x[2][NB2][STAGE_K];   // 2 x 16 KB

    const int ks   = blockIdx.x;
    const int og   = blockIdx.y;
    const int tid  = threadIdx.x;
    const int warp = tid >> 5;
    const int lane = tid & 31;
    const int o0   = og * TOB + warp * TOW;
    const int kbase = ks * K_CHUNK;                 // within one channel (1024 | 4096)
    const int mbase = kbase & (LL - 1);

    // staging: this warp handles batch pair b2s = warp, channel ich
    const int ich = kbase >> 12;
    const float* __restrict__ xlo = x + ((size_t)(2 * warp) * NCIN + ich) * LL;
    const float* __restrict__ xhi = xlo + (size_t)KTOT;   // next batch, same channel

    const float2* __restrict__ w2 = reinterpret_cast<const float2*>(w);
    const size_t wrow = KTOT / 2;
    const int kg2base = (kbase >> 1) + lane;

    // stage S of x -> smem buffer BUF via 4B cp.async with reversal
#define PREF(S, BUF)                                                            \
    {                                                                           \
        const int M0 = LL - (mbase + (S) * STAGE_K);                            \
        _Pragma("unroll")                                                       \
        for (int e = 0; e < 8; e++) {                                           \
            int kk   = lane + 32 * e;                                           \
            int msrc = (M0 - kk) & (LL - 1);                                    \
            uint32_t dlo = (uint32_t)__cvta_generic_to_shared(                  \
                &s_x[BUF][warp][kk]);                                           \
            asm volatile("cp.async.ca.shared.global [%0], [%1], 4;\n"           \
                         :: "r"(dlo), "l"(xlo + msrc));                         \
            asm volatile("cp.async.ca.shared.global [%0], [%1], 4;\n"           \
                         :: "r"(dlo + 4), "l"(xhi + msrc));                     \
        }                                                                       \
        asm volatile("cp.async.commit_group;\n");                               \
    }

    // prologue: stage 0 + first w iter
    PREF(0, 0);

    float2 wv[2][TOW];
#pragma unroll
    for (int o = 0; o < TOW; o++)
        wv[0][o] = __ldg(&w2[(size_t)(o0 + o) * wrow + kg2base]);

    unsigned long long acc[NB2][TOW];
#pragma unroll
    for (int b = 0; b < NB2; b++)
#pragma unroll
        for (int o = 0; o < TOW; o++) acc[b][o] = 0ull;

    asm volatile("cp.async.wait_group 0;\n");
    __syncthreads();

#pragma unroll
    for (int g = 0; g < ITERS; g++) {
        const int s   = g >> 2;
        const int j   = g & 3;
        const int cur = g & 1;
        const int buf = s & 1;

        // kick off next x stage at the start of this stage's compute
        if (j == 0 && s + 1 < NSTAGES) PREF(s + 1, (s + 1) & 1);

        // prefetch next iter's w into the other register buffer
        if (g + 1 < ITERS) {
            const int kg2n = kg2base + (g + 1) * 32;
#pragma unroll
            for (int o = 0; o < TOW; o++)
                wv[(g + 1) & 1][o] = __ldg(&w2[(size_t)(o0 + o) * wrow + kg2n]);
        }

        const int kloc = (j * 32 + lane) * 2;

        ulonglong2 xv[NB2];
#pragma unroll
        for (int b = 0; b < NB2; b++)
            xv[b] = *reinterpret_cast<const ulonglong2*>(&s_x[buf][b][kloc]);

#pragma unroll
        for (int o = 0; o < TOW; o++) {
            unsigned long long wd0 = dup_f32x2(wv[cur][o].x);
            unsigned long long wd1 = dup_f32x2(wv[cur][o].y);
#pragma unroll
            for (int b = 0; b < NB2; b++) {
                fma_f32x2(acc[b][o], xv[b].x, wd0);
                fma_f32x2(acc[b][o], xv[b].y, wd1);
            }
        }

        // publish next stage at the end of this stage
        if (j == 3 && s + 1 < NSTAGES) {
            asm volatile("cp.async.wait_group 0;\n");
            __syncthreads();
        }
    }
#undef PREF

    // Value-splitting butterfly: 64 accs -> lane l ends with accs 2l, 2l+1
    // fully reduced over all 32 lanes.
    unsigned long long vals[64];
#pragma unroll
    for (int b = 0; b < NB2; b++)
#pragma unroll
        for (int o = 0; o < TOW; o++) vals[b * TOW + o] = acc[b][o];

#define RSTEP(OFF, CNT)                                                         \
    {                                                                           \
        const bool up = (lane & (OFF)) != 0;                                    \
        _Pragma("unroll")                                                       \
        for (int j2 = 0; j2 < (CNT); j2++) {                                    \
            unsigned long long send = up ? vals[j2] : vals[j2 + (CNT)];         \
            unsigned long long recv = __shfl_xor_sync(0xffffffffu, send, OFF);  \
            unsigned long long keep = up ? vals[j2 + (CNT)] : vals[j2];         \
            add_f32x2(keep, recv);                                              \
            vals[j2] = keep;                                                    \
        }                                                                       \
    }
    RSTEP(16, 32)
    RSTEP(8, 16)
    RSTEP(4, 8)
    RSTEP(2, 4)
    RSTEP(1, 2)
#undef RSTEP

#pragma unroll
    for (int j2 = 0; j2 < 2; j2++) {
        int a  = 2 * lane + j2;
        int b2 = a >> 3;                               // vals layout [b2][o]
        int o  = a & 7;
        int oo = o0 + o;
        float2 v;
        asm("mov.b64 {%0, %1}, %2;" : "=f"(v.x), "=f"(v.y) : "l"(vals[j2]));
        g_part[((size_t)(2 * b2)     * NCOUT + oo) * KS + ks] = v.x;
        g_part[((size_t)(2 * b2 + 1) * NCOUT + oo) * KS + ks] = v.y;
    }
}

// ---------------------------------------------------------------------------
// Deterministic reduction over k-splits + bias. One warp per output, coalesced.
// ---------------------------------------------------------------------------
__global__ void reduce_kernel(const float* __restrict__ bias,
                              float* __restrict__ out) {
    int gw   = (blockIdx.x * blockDim.x + threadIdx.x) >> 5;  // output index
    int lane = threadIdx.x & 31;
    if (gw >= NB * NCOUT) return;
    const float* p = g_part + (size_t)gw * KS;
    float s = 0.0f;
#pragma unroll
    for (int i = 0; i < KS / 32; i++) s += p[i * 32 + lane];
#pragma unroll
    for (int off = 16; off > 0; off >>= 1)
        s += __shfl_xor_sync(0xffffffffu, s, off);
    if (lane == 0) out[gw] = s + bias[gw & (NCOUT - 1)];
}

// ---------------------------------------------------------------------------
extern "C" void kernel_launch(void* const* d_in, const int* in_sizes, int n_in,
                              void* d_out, int out_size) {
    const float* x    = (const float*)d_in[0];   // [16, 128, 4096]
    const float* w    = (const float*)d_in[1];   // [128, 128, 4096]
    const float* bias = (const float*)d_in[2];   // [128]
    float* out = (float*)d_out;                  // [16, 128, 1]

    dim3 grid(KS, OGROUPS);
    gemm_kernel<<<grid, 256>>>(x, w);

    reduce_kernel<<<(NB * NCOUT * 32) / 256, 256>>>(bias, out);
}

// round 4
// speedup vs baseline: 1.3656x; 1.0035x over previous
#include <cuda_runtime.h>
#include <cstdint>

// Problem constants
constexpr int LL    = 4096;
constexpr int NB    = 16;
constexpr int NCIN  = 128;
constexpr int NCOUT = 128;
constexpr int KTOT  = NCIN * LL;            // 524288
constexpr int NB2   = NB / 2;               // 8 batch pairs (f32x2 packing)

// GEMM blocking
constexpr int KS        = 512;              // k-split blocks (each within one channel)
constexpr int K_CHUNK   = KTOT / KS;        // 1024
constexpr int STAGE_K   = 256;              // k per smem stage
constexpr int NSTAGES   = K_CHUNK / STAGE_K;// 4
constexpr int ITERS     = K_CHUNK / 64;     // 16 compute iters (64 k each)
constexpr int TOW       = 8;                // outputs per warp
constexpr int TOB       = 64;               // outputs per block
constexpr int OGROUPS   = NCOUT / TOB;      // 2

// Scratch (allocation-free)
__device__ float g_part[NB * NCOUT * KS];   // 4 MB, layout [b*NCOUT+o][ks]

__device__ __forceinline__ unsigned long long dup_f32x2(float v) {
    unsigned long long r;
    asm("mov.b64 %0, {%1, %1};" : "=l"(r) : "f"(v));
    return r;
}
__device__ __forceinline__ void fma_f32x2(unsigned long long& d,
                                          unsigned long long a,
                                          unsigned long long b) {
    asm("fma.rn.f32x2 %0, %1, %2, %0;" : "+l"(d) : "l"(a), "l"(b));
}
__device__ __forceinline__ void add_f32x2(unsigned long long& d,
                                          unsigned long long a) {
    asm("add.rn.f32x2 %0, %0, %1;" : "+l"(d) : "l"(a));
}

// ---------------------------------------------------------------------------
// Fused GEMM: out[b,o] = sum_k x[b, rev(k)] * w[o, k], split-K over 512 blocks.
// The index reversal (circular correlation at lag 0) is applied during smem
// staging, done with 4-byte cp.async gathers (descending-contiguous sources).
// 8 warps x 8 outputs; batches packed pairwise into f32x2 accumulators.
// Warp b2s==warp stages batch-pair `warp`'s slice each stage.
// ---------------------------------------------------------------------------
__global__ __launch_bounds__(256, 1) void gemm_kernel(const float* __restrict__ x,
                                                      const float* __restrict__ w) {
    __shared__ __align__(16) float2 s_x[2][NB2][STAGE_K];   // 2 x 16 KB

    const int ks   = blockIdx.x;
    const int og   = blockIdx.y;
    const int tid  = threadIdx.x;
    const int warp = tid >> 5;
    const int lane = tid & 31;
    const int o0   = og * TOB + warp * TOW;
    const int kbase = ks * K_CHUNK;                 // within one channel (1024 | 4096)
    const int mbase = kbase & (LL - 1);

    // staging: this warp handles batch pair b2s = warp, channel ich
    const int ich = kbase >> 12;
    const float* __restrict__ xlo = x + ((size_t)(2 * warp) * NCIN + ich) * LL;
    const float* __restrict__ xhi = xlo + (size_t)KTOT;   // next batch, same channel

    const float2* __restrict__ w2 = reinterpret_cast<const float2*>(w);
    const size_t wrow = KTOT / 2;
    const int kg2base = (kbase >> 1) + lane;

    // stage S of x -> smem buffer BUF via 4B cp.async with reversal
#define PREF(S, BUF)                                                            \
    {                                                                           \
        const int M0 = LL - (mbase + (S) * STAGE_K);                            \
        _Pragma("unroll")                                                       \
        for (int e = 0; e < 8; e++) {                                           \
            int kk   = lane + 32 * e;                                           \
            int msrc = (M0 - kk) & (LL - 1);                                    \
            uint32_t dlo = (uint32_t)__cvta_generic_to_shared(                  \
                &s_x[BUF][warp][kk]);                                           \
            asm volatile("cp.async.ca.shared.global [%0], [%1], 4;\n"           \
                         :: "r"(dlo), "l"(xlo + msrc));                         \
            asm volatile("cp.async.ca.shared.global [%0], [%1], 4;\n"           \
                         :: "r"(dlo + 4), "l"(xhi + msrc));                     \
        }                                                                       \
        asm volatile("cp.async.commit_group;\n");                               \
    }

    // prologue: stage 0 + first w iter
    PREF(0, 0);

    float2 wv[2][TOW];
#pragma unroll
    for (int o = 0; o < TOW; o++)
        wv[0][o] = __ldg(&w2[(size_t)(o0 + o) * wrow + kg2base]);

    unsigned long long acc[NB2][TOW];
#pragma unroll
    for (int b = 0; b < NB2; b++)
#pragma unroll
        for (int o = 0; o < TOW; o++) acc[b][o] = 0ull;

    asm volatile("cp.async.wait_group 0;\n");
    __syncthreads();

#pragma unroll
    for (int g = 0; g < ITERS; g++) {
        const int s   = g >> 2;
        const int j   = g & 3;
        const int cur = g & 1;
        const int buf = s & 1;

        // kick off next x stage at the start of this stage's compute
        if (j == 0 && s + 1 < NSTAGES) PREF(s + 1, (s + 1) & 1);

        // prefetch next iter's w into the other register buffer
        if (g + 1 < ITERS) {
            const int kg2n = kg2base + (g + 1) * 32;
#pragma unroll
            for (int o = 0; o < TOW; o++)
                wv[(g + 1) & 1][o] = __ldg(&w2[(size_t)(o0 + o) * wrow + kg2n]);
        }

        const int kloc = (j * 32 + lane) * 2;

        ulonglong2 xv[NB2];
#pragma unroll
        for (int b = 0; b < NB2; b++)
            xv[b] = *reinterpret_cast<const ulonglong2*>(&s_x[buf][b][kloc]);

#pragma unroll
        for (int o = 0; o < TOW; o++) {
            unsigned long long wd0 = dup_f32x2(wv[cur][o].x);
            unsigned long long wd1 = dup_f32x2(wv[cur][o].y);
#pragma unroll
            for (int b = 0; b < NB2; b++) {
                fma_f32x2(acc[b][o], xv[b].x, wd0);
                fma_f32x2(acc[b][o], xv[b].y, wd1);
            }
        }

        // publish next stage at the end of this stage
        if (j == 3 && s + 1 < NSTAGES) {
            asm volatile("cp.async.wait_group 0;\n");
            __syncthreads();
        }
    }
#undef PREF

    // Value-splitting butterfly: 64 accs -> lane l ends with accs 2l, 2l+1
    // fully reduced over all 32 lanes.
    unsigned long long vals[64];
#pragma unroll
    for (int b = 0; b < NB2; b++)
#pragma unroll
        for (int o = 0; o < TOW; o++) vals[b * TOW + o] = acc[b][o];

#define RSTEP(OFF, CNT)                                                         \
    {                                                                           \
        const bool up = (lane & (OFF)) != 0;                                    \
        _Pragma("unroll")                                                       \
        for (int j2 = 0; j2 < (CNT); j2++) {                                    \
            unsigned long long send = up ? vals[j2] : vals[j2 + (CNT)];         \
            unsigned long long recv = __shfl_xor_sync(0xffffffffu, send, OFF);  \
            unsigned long long keep = up ? vals[j2 + (CNT)] : vals[j2];         \
            add_f32x2(keep, recv);                                              \
            vals[j2] = keep;                                                    \
        }                                                                       \
    }
    RSTEP(16, 32)
    RSTEP(8, 16)
    RSTEP(4, 8)
    RSTEP(2, 4)
    RSTEP(1, 2)
#undef RSTEP

#pragma unroll
    for (int j2 = 0; j2 < 2; j2++) {
        int a  = 2 * lane + j2;
        int b2 = a >> 3;                               // vals layout [b2][o]
        int o  = a & 7;
        int oo = o0 + o;
        float2 v;
        asm("mov.b64 {%0, %1}, %2;" : "=f"(v.x), "=f"(v.y) : "l"(vals[j2]));
        g_part[((size_t)(2 * b2)     * NCOUT + oo) * KS + ks] = v.x;
        g_part[((size_t)(2 * b2 + 1) * NCOUT + oo) * KS + ks] = v.y;
    }
}

// ---------------------------------------------------------------------------
// Deterministic reduction over k-splits + bias. One warp per output, coalesced.
// ---------------------------------------------------------------------------
__global__ void reduce_kernel(const float* __restrict__ bias,
                              float* __restrict__ out) {
    int gw   = (blockIdx.x * blockDim.x + threadIdx.x) >> 5;  // output index
    int lane = threadIdx.x & 31;
    if (gw >= NB * NCOUT) return;
    const float* p = g_part + (size_t)gw * KS;
    float s = 0.0f;
#pragma unroll
    for (int i = 0; i < KS / 32; i++) s += p[i * 32 + lane];
#pragma unroll
    for (int off = 16; off > 0; off >>= 1)
        s += __shfl_xor_sync(0xffffffffu, s, off);
    if (lane == 0) out[gw] = s + bias[gw & (NCOUT - 1)];
}

// ---------------------------------------------------------------------------
extern "C" void kernel_launch(void* const* d_in, const int* in_sizes, int n_in,
                              void* d_out, int out_size) {
    const float* x    = (const float*)d_in[0];   // [16, 128, 4096]
    const float* w    = (const float*)d_in[1];   // [128, 128, 4096]
    const float* bias = (const float*)d_in[2];   // [128]
    float* out = (float*)d_out;                  // [16, 128, 1]

    dim3 grid(KS, OGROUPS);
    gemm_kernel<<<grid, 256>>>(x, w);

    reduce_kernel<<<(NB * NCOUT * 32) / 256, 256>>>(bias, out);
}

// round 5
// speedup vs baseline: 1.3661x; 1.0004x over previous
#include <cuda_runtime.h>
#include <cstdint>

// Problem constants
constexpr int LL    = 4096;
constexpr int NB    = 16;
constexpr int NCIN  = 128;
constexpr int NCOUT = 128;
constexpr int KTOT  = NCIN * LL;            // 524288
constexpr int NB2   = NB / 2;               // 8 batch pairs (f32x2 packing)

// GEMM blocking
constexpr int KS        = 512;              // k-split blocks (each within one channel)
constexpr int K_CHUNK   = KTOT / KS;        // 1024
constexpr int STAGE_K   = 256;              // k per smem stage
constexpr int NSTAGES   = K_CHUNK / STAGE_K;// 4
constexpr int ITERS     = K_CHUNK / 64;     // 16 compute iters (64 k each)
constexpr int TOW       = 8;                // outputs per warp
constexpr int TOB       = 64;               // outputs per block
constexpr int OGROUPS   = NCOUT / TOB;      // 2

// Scratch (allocation-free)
__device__ float g_part[NB * NCOUT * KS];   // 4 MB, layout [b*NCOUT+o][ks]

__device__ __forceinline__ unsigned long long dup_f32x2(float v) {
    unsigned long long r;
    asm("mov.b64 %0, {%1, %1};" : "=l"(r) : "f"(v));
    return r;
}
__device__ __forceinline__ void fma_f32x2(unsigned long long& d,
                                          unsigned long long a,
                                          unsigned long long b) {
    asm("fma.rn.f32x2 %0, %1, %2, %0;" : "+l"(d) : "l"(a), "l"(b));
}
__device__ __forceinline__ void add_f32x2(unsigned long long& d,
                                          unsigned long long a) {
    asm("add.rn.f32x2 %0, %0, %1;" : "+l"(d) : "l"(a));
}

// ---------------------------------------------------------------------------
// Fused GEMM: out[b,o] = sum_k x[b, rev(k)] * w[o, k], split-K over 512 blocks.
// The index reversal (circular correlation at lag 0) is applied during smem
// staging, done with 4-byte cp.async gathers (descending-contiguous sources).
// 8 warps x 8 outputs; batches packed pairwise into f32x2 accumulators.
// Warp b2s==warp stages batch-pair `warp`'s slice each stage.
// ---------------------------------------------------------------------------
__global__ __launch_bounds__(256, 1) void gemm_kernel(const float* __restrict__ x,
                                                      const float* __restrict__ w) {
    __shared__ __align__(16) float2 s_x[2][NB2][STAGE_K];   // 2 x 16 KB

    const int ks   = blockIdx.x;
    const int og   = blockIdx.y;
    const int tid  = threadIdx.x;
    const int warp = tid >> 5;
    const int lane = tid & 31;
    const int o0   = og * TOB + warp * TOW;
    const int kbase = ks * K_CHUNK;                 // within one channel (1024 | 4096)
    const int mbase = kbase & (LL - 1);

    // staging: this warp handles batch pair b2s = warp, channel ich
    const int ich = kbase >> 12;
    const float* __restrict__ xlo = x + ((size_t)(2 * warp) * NCIN + ich) * LL;
    const float* __restrict__ xhi = xlo + (size_t)KTOT;   // next batch, same channel

    const float2* __restrict__ w2 = reinterpret_cast<const float2*>(w);
    const size_t wrow = KTOT / 2;
    const int kg2base = (kbase >> 1) + lane;

    // stage S of x -> smem buffer BUF via 4B cp.async with reversal
#define PREF(S, BUF)                                                            \
    {                                                                           \
        const int M0 = LL - (mbase + (S) * STAGE_K);                            \
        _Pragma("unroll")                                                       \
        for (int e = 0; e < 8; e++) {                                           \
            int kk   = lane + 32 * e;                                           \
            int msrc = (M0 - kk) & (LL - 1);                                    \
            uint32_t dlo = (uint32_t)__cvta_generic_to_shared(                  \
                &s_x[BUF][warp][kk]);                                           \
            asm volatile("cp.async.ca.shared.global [%0], [%1], 4;\n"           \
                         :: "r"(dlo), "l"(xlo + msrc));                         \
            asm volatile("cp.async.ca.shared.global [%0], [%1], 4;\n"           \
                         :: "r"(dlo + 4), "l"(xhi + msrc));                     \
        }                                                                       \
        asm volatile("cp.async.commit_group;\n");                               \
    }

    // prologue: stage 0 + first w iter
    PREF(0, 0);

    float2 wv[2][TOW];
#pragma unroll
    for (int o = 0; o < TOW; o++)
        wv[0][o] = __ldg(&w2[(size_t)(o0 + o) * wrow + kg2base]);

    unsigned long long acc[NB2][TOW];
#pragma unroll
    for (int b = 0; b < NB2; b++)
#pragma unroll
        for (int o = 0; o < TOW; o++) acc[b][o] = 0ull;

    asm volatile("cp.async.wait_group 0;\n");
    __syncthreads();

#pragma unroll
    for (int g = 0; g < ITERS; g++) {
        const int s   = g >> 2;
        const int j   = g & 3;
        const int cur = g & 1;
        const int buf = s & 1;

        // kick off next x stage at the start of this stage's compute
        if (j == 0 && s + 1 < NSTAGES) PREF(s + 1, (s + 1) & 1);

        // prefetch next iter's w into the other register buffer
        if (g + 1 < ITERS) {
            const int kg2n = kg2base + (g + 1) * 32;
#pragma unroll
            for (int o = 0; o < TOW; o++)
                wv[(g + 1) & 1][o] = __ldg(&w2[(size_t)(o0 + o) * wrow + kg2n]);
        }

        const int kloc = (j * 32 + lane) * 2;

        ulonglong2 xv[NB2];
#pragma unroll
        for (int b = 0; b < NB2; b++)
            xv[b] = *reinterpret_cast<const ulonglong2*>(&s_x[buf][b][kloc]);

#pragma unroll
        for (int o = 0; o < TOW; o++) {
            unsigned long long wd0 = dup_f32x2(wv[cur][o].x);
            unsigned long long wd1 = dup_f32x2(wv[cur][o].y);
#pragma unroll
            for (int b = 0; b < NB2; b++) {
                fma_f32x2(acc[b][o], xv[b].x, wd0);
                fma_f32x2(acc[b][o], xv[b].y, wd1);
            }
        }

        // publish next stage at the end of this stage
        if (j == 3 && s + 1 < NSTAGES) {
            asm volatile("cp.async.wait_group 0;\n");
            __syncthreads();
        }
    }
#undef PREF

    // Value-splitting butterfly: 64 accs -> lane l ends with accs 2l, 2l+1
    // fully reduced over all 32 lanes.
    unsigned long long vals[64];
#pragma unroll
    for (int b = 0; b < NB2; b++)
#pragma unroll
        for (int o = 0; o < TOW; o++) vals[b * TOW + o] = acc[b][o];

#define RSTEP(OFF, CNT)                                                         \
    {                                                                           \
        const bool up = (lane & (OFF)) != 0;                                    \
        _Pragma("unroll")                                                       \
        for (int j2 = 0; j2 < (CNT); j2++) {                                    \
            unsigned long long send = up ? vals[j2] : vals[j2 + (CNT)];         \
            unsigned long long recv = __shfl_xor_sync(0xffffffffu, send, OFF);  \
            unsigned long long keep = up ? vals[j2 + (CNT)] : vals[j2];         \
            add_f32x2(keep, recv);                                              \
            vals[j2] = keep;                                                    \
        }                                                                       \
    }
    RSTEP(16, 32)
    RSTEP(8, 16)
    RSTEP(4, 8)
    RSTEP(2, 4)
    RSTEP(1, 2)
#undef RSTEP

#pragma unroll
    for (int j2 = 0; j2 < 2; j2++) {
        int a  = 2 * lane + j2;
        int b2 = a >> 3;                               // vals layout [b2][o]
        int o  = a & 7;
        int oo = o0 + o;
        float2 v;
        asm("mov.b64 {%0, %1}, %2;" : "=f"(v.x), "=f"(v.y) : "l"(vals[j2]));
        g_part[((size_t)(2 * b2)     * NCOUT + oo) * KS + ks] = v.x;
        g_part[((size_t)(2 * b2 + 1) * NCOUT + oo) * KS + ks] = v.y;
    }
}

// ---------------------------------------------------------------------------
// Deterministic reduction over k-splits + bias. One warp per output, coalesced.
// ---------------------------------------------------------------------------
__global__ void reduce_kernel(const float* __restrict__ bias,
                              float* __restrict__ out) {
    int gw   = (blockIdx.x * blockDim.x + threadIdx.x) >> 5;  // output index
    int lane = threadIdx.x & 31;
    if (gw >= NB * NCOUT) return;
    const float* p = g_part + (size_t)gw * KS;
    float s = 0.0f;
#pragma unroll
    for (int i = 0; i < KS / 32; i++) s += p[i * 32 + lane];
#pragma unroll
    for (int off = 16; off > 0; off >>= 1)
        s += __shfl_xor_sync(0xffffffffu, s, off);
    if (lane == 0) out[gw] = s + bias[gw & (NCOUT - 1)];
}

// ---------------------------------------------------------------------------
extern "C" void kernel_launch(void* const* d_in, const int* in_sizes, int n_in,
                              void* d_out, int out_size) {
    const float* x    = (const float*)d_in[0];   // [16, 128, 4096]
    const float* w    = (const float*)d_in[1];   // [128, 128, 4096]
    const float* bias = (const float*)d_in[2];   // [128]
    float* out = (float*)d_out;                  // [16, 128, 1]

    dim3 grid(KS, OGROUPS);
    gemm_kernel<<<grid, 256>>>(x, w);

    reduce_kernel<<<(NB * NCOUT * 32) / 256, 256>>>(bias, out);
}